// round 1
// baseline (speedup 1.0000x reference)
#include <cuda_runtime.h>
#include <math.h>
#include <math_constants.h>

#define BS 16
#define Q 900
#define NC 92
#define T 100
#define NT (BS * T)   // 1600

// Transposed per-batch cost slice: ct[b][t][q] = C[b, q, b*T + t]
// (own-batch targets only). Contiguous in q for coalesced row scans in LSA.
__device__ float g_ct[BS][T][Q];

// ---------------------------------------------------------------------------
// Kernel 1: cost matrix. One block per (b,q). Threads stride the 1600 targets.
// ---------------------------------------------------------------------------
__global__ void __launch_bounds__(256) cost_kernel(
    const float* __restrict__ logits,   // [BS*Q, NC]
    const float* __restrict__ pboxes,   // [BS*Q, 4]  cxcywh
    const int*   __restrict__ tgt_ids,  // [NT]
    const float* __restrict__ tbox,     // [NT, 4]    xyxy
    float* __restrict__ C)              // [BS*Q, NT]
{
    const int bq  = blockIdx.x;
    const int b   = bq / Q;
    const int q   = bq - b * Q;
    const int tid = threadIdx.x;

    __shared__ float sl[NC];
    __shared__ float smax, ssum;

    const float* L = logits + (size_t)bq * NC;
    if (tid < NC) sl[tid] = L[tid];
    __syncthreads();

    if (tid < 32) {
        float m = -CUDART_INF_F;
        for (int c = tid; c < NC; c += 32) m = fmaxf(m, sl[c]);
        #pragma unroll
        for (int o = 16; o; o >>= 1) m = fmaxf(m, __shfl_xor_sync(0xffffffffu, m, o));
        float s = 0.f;
        for (int c = tid; c < NC; c += 32) s += expf(sl[c] - m);
        #pragma unroll
        for (int o = 16; o; o >>= 1) s += __shfl_xor_sync(0xffffffffu, s, o);
        if (tid == 0) { smax = m; ssum = s; }
    }
    __syncthreads();

    const float m   = smax;
    const float sum = ssum;

    const float cx = pboxes[bq * 4 + 0];
    const float cy = pboxes[bq * 4 + 1];
    const float w  = pboxes[bq * 4 + 2];
    const float h  = pboxes[bq * 4 + 3];
    // pred xyxy (compute from cxcywh exactly like the reference: c - s/2, c + s/2)
    const float px0 = cx - w * 0.5f, py0 = cy - h * 0.5f;
    const float px1 = cx + w * 0.5f, py1 = cy + h * 0.5f;
    const float area_a = (px1 - px0) * (py1 - py0);

    float* Crow = C + (size_t)bq * NT;

    for (int j = tid; j < NT; j += 256) {
        const int id = tgt_ids[j];
        const float prob = expf(sl[id] - m) / sum;

        const float tx0 = tbox[j * 4 + 0], ty0 = tbox[j * 4 + 1];
        const float tx1 = tbox[j * 4 + 2], ty1 = tbox[j * 4 + 3];

        // target cxcywh (xyxy -> cxcywh, as the reference does for cost_bbox)
        const float tcx = (tx0 + tx1) * 0.5f, tcy = (ty0 + ty1) * 0.5f;
        const float tw  = tx1 - tx0,          th  = ty1 - ty0;

        const float cb = fabsf(cx - tcx) + fabsf(cy - tcy) + fabsf(w - tw) + fabsf(h - th);

        // GIoU: pred xyxy vs target xyxy
        const float area_b = (tx1 - tx0) * (ty1 - ty0);
        const float ltx = fmaxf(px0, tx0), lty = fmaxf(py0, ty0);
        const float rbx = fminf(px1, tx1), rby = fminf(py1, ty1);
        const float iw = fmaxf(rbx - ltx, 0.f), ih = fmaxf(rby - lty, 0.f);
        const float inter = iw * ih;
        const float uni = area_a + area_b - inter;
        const float iou = inter / uni;
        const float lcx = fminf(px0, tx0), lcy = fminf(py0, ty0);
        const float rcx = fmaxf(px1, tx1), rcy = fmaxf(py1, ty1);
        const float cw = fmaxf(rcx - lcx, 0.f), ch = fmaxf(rcy - lcy, 0.f);
        const float ac = cw * ch;
        const float giou = iou - (ac - uni) / ac;

        // C = 5*cost_bbox + 1*cost_class + 2*cost_giou
        float cost = 5.0f * cb + (-prob);
        cost = cost + 2.0f * (-giou);

        Crow[j] = cost;

        const int tl = j - b * T;
        if (tl >= 0 && tl < T) g_ct[b][tl][q] = cost;
    }
}

// ---------------------------------------------------------------------------
// Kernel 2: Jonker-Volgenant shortest augmenting path LSA, one block per batch.
// Exactly mirrors the reference's update order and first-min-index tiebreak.
// n = T (rows = targets), m = Q (cols = preds). Column j owned by thread j.
// ---------------------------------------------------------------------------
__device__ __forceinline__ void amin_combine(float& v, int& i, float v2, int i2) {
    if (v2 < v || (v2 == v && i2 < i)) { v = v2; i = i2; }
}

__global__ void __launch_bounds__(1024) lsa_kernel(
    float* __restrict__ rows_out,   // [BS*T]
    float* __restrict__ cols_out)   // [BS*T]
{
    const int b   = blockIdx.x;
    const int tid = threadIdx.x;

    __shared__ float u[T + 1];
    __shared__ int   p[Q + 1];
    __shared__ int   sway[Q + 1];
    __shared__ float red_v[32];
    __shared__ int   red_i[32];
    __shared__ int   sj0, si0, sj1, srun;
    __shared__ float sdelta, su_i0;
    __shared__ int   ans[T];

    // init
    if (tid <= T) u[tid] = 0.f;
    if (tid <= Q) { p[tid] = 0; sway[tid] = 0; }
    float v_j = 0.f;                 // v[tid], valid for tid <= Q
    __syncthreads();

    const int lane = tid & 31;
    const int wid  = tid >> 5;

    for (int i = 1; i <= T; ++i) {
        float minv = CUDART_INF_F;
        bool  used = false;
        if (tid == 0) { p[0] = i; sj0 = 0; }
        __syncthreads();

        while (true) {
            const int j0 = sj0;
            if (tid == j0) used = true;
            if (tid == 0) { si0 = p[j0]; su_i0 = u[p[j0]]; }
            __syncthreads();

            const int   i0   = si0;
            const float u_i0 = su_i0;
            const float* crow = &g_ct[b][i0 - 1][0];

            float val = CUDART_INF_F;
            int   idx = Q + 1;
            if (tid >= 1 && tid <= Q && !used) {
                const float cur = __ldg(crow + (tid - 1)) - u_i0 - v_j;
                if (cur < minv) { minv = cur; sway[tid] = j0; }
                val = minv;
                idx = tid;
            }

            // block argmin with smallest-index tiebreak (np.argmin semantics)
            #pragma unroll
            for (int o = 16; o; o >>= 1) {
                const float v2 = __shfl_xor_sync(0xffffffffu, val, o);
                const int   i2 = __shfl_xor_sync(0xffffffffu, idx, o);
                amin_combine(val, idx, v2, i2);
            }
            if (lane == 0) { red_v[wid] = val; red_i[wid] = idx; }
            __syncthreads();
            if (wid == 0) {
                val = red_v[lane];
                idx = red_i[lane];
                #pragma unroll
                for (int o = 16; o; o >>= 1) {
                    const float v2 = __shfl_xor_sync(0xffffffffu, val, o);
                    const int   i2 = __shfl_xor_sync(0xffffffffu, idx, o);
                    amin_combine(val, idx, v2, i2);
                }
                if (lane == 0) { sdelta = val; sj1 = idx; }
            }
            __syncthreads();

            const float delta = sdelta;
            const int   j1    = sj1;

            if (tid <= Q) {
                if (used) {
                    u[p[tid]] += delta;   // distinct rows among used columns -> race-free
                    v_j -= delta;
                } else if (tid >= 1) {
                    minv -= delta;
                }
            }
            if (tid == 0) { sj0 = j1; srun = (p[j1] != 0); }
            __syncthreads();
            if (!srun) break;
        }

        // augment (serial, short path)
        if (tid == 0) {
            int j0a = sj0;
            while (j0a) {
                const int j1a = sway[j0a];
                p[j0a] = p[j1a];
                j0a = j1a;
            }
        }
        __syncthreads();
    }

    // extract assignment: ans[t] = pred column assigned to target t
    if (tid >= 1 && tid <= Q) {
        const int r = p[tid];
        if (r > 0) ans[r - 1] = tid - 1;
    }
    __syncthreads();

    // rows = sorted pred indices, cols = targets ordered by their pred index
    if (tid < T) {
        const int a = ans[tid];
        int rank = 0;
        #pragma unroll 4
        for (int t = 0; t < T; ++t) rank += (ans[t] < a);
        rows_out[b * T + rank] = (float)a;
        cols_out[b * T + rank] = (float)tid;
    }
}

// ---------------------------------------------------------------------------
extern "C" void kernel_launch(void* const* d_in, const int* in_sizes, int n_in,
                              void* d_out, int out_size) {
    const float* logits = (const float*)d_in[0];
    const float* pboxes = (const float*)d_in[1];
    const int*   ids    = (const int*)d_in[2];
    const float* tbox   = (const float*)d_in[3];
    float* out = (float*)d_out;

    const long long CN = (long long)BS * Q * NT;   // 23,040,000

    cost_kernel<<<BS * Q, 256>>>(logits, pboxes, ids, tbox, out);

    if ((long long)out_size >= CN + 2LL * BS * T) {
        lsa_kernel<<<BS, 1024>>>(out + CN, out + CN + (long long)BS * T);
    }
}